// round 10
// baseline (speedup 1.0000x reference)
#include <cuda_runtime.h>
#include <cuda_bf16.h>

// Mask_based_WSM reduces to:  out0 = sigmoid(2*x - 1),  out1 = 1 - out0.
// (histogram/mask path is a global per-batch predicate that always selects
//  the identity branch; image_vis is unused.)
//
// R7 theory: input (64MB) is identical across graph replays and L2 is 126MB.
// Cache loads in L2 (__ldcg) so replays hit L2 instead of DRAM; keep stores
// evict-first (__stcs) so the 128MB of write-once lines don't evict the input.
// Steady-state DRAM traffic: 192MB -> ~128MB per replay.

__device__ __forceinline__ float sig2m1(float x) {
    float t = __fmaf_rn(2.0f, x, -1.0f);
    return __fdividef(1.0f, 1.0f + __expf(-t));
}

__global__ __launch_bounds__(256)
void wsm_kernel(const float* __restrict__ in,
                float* __restrict__ out0,
                float* __restrict__ out1,
                int n4, int tail_start, int n) {
    int i = blockIdx.x * blockDim.x + threadIdx.x;

    if (i < n4) {
        const float4* in4 = (const float4*)in;
        float4 x = __ldcg(&in4[i]);          // L2-resident across replays
        float4 a, b;
        a.x = sig2m1(x.x);  b.x = 1.0f - a.x;
        a.y = sig2m1(x.y);  b.y = 1.0f - a.y;
        a.z = sig2m1(x.z);  b.z = 1.0f - a.z;
        a.w = sig2m1(x.w);  b.w = 1.0f - a.w;
        __stcs(&((float4*)out0)[i], a);      // evict-first: protect input lines
        __stcs(&((float4*)out1)[i], b);
    }

    // Tail (n % 4 != 0): first threads of block 0. Empty for 16x1x1024x1024.
    if (blockIdx.x == 0) {
        int t = tail_start + threadIdx.x;
        if (t < n) {
            float s = sig2m1(in[t]);
            out0[t] = s;
            out1[t] = 1.0f - s;
        }
    }
}

extern "C" void kernel_launch(void* const* d_in, const int* in_sizes, int n_in,
                              void* d_out, int out_size) {
    const float* irr = (const float*)d_in[0];   // image_irr (image_vis unused)
    float* out = (float*)d_out;
    int n = in_sizes[0];                         // 16 * 1 * 1024 * 1024

    float* o0 = out;        // msks[0]
    float* o1 = out + n;    // msks[1]

    int n4 = n >> 2;
    int tail_start = n4 << 2;

    int threads = 256;
    int blocks = (n4 + threads - 1) / threads;
    if (blocks < 1) blocks = 1;
    wsm_kernel<<<blocks, threads>>>(irr, o0, o1, n4, tail_start, n);
}